// round 2
// baseline (speedup 1.0000x reference)
#include <cuda_runtime.h>
#include <cstdint>

// Problem constants (fixed by reference): B=8, C=128, H=W=128, HEADS=8
#define HEADS_TOTAL 64     // B * HEADS
#define CH 16              // channels per head (hk = hv = 16)
#define NN 16384           // H * W
#define CHUNKS 8           // n-chunks per head in pass 1
#define CN (NN / CHUNKS)   // 2048 n per chunk

// Scratch (no allocations allowed): per-(head,chunk) partials and reduced ctx/S.
// Partial layout per (head,chunk): [0..255] = ctxU[k][v] (k*16+v), [256..271] = S[k]
__device__ float g_part[HEADS_TOTAL * CHUNKS * 272];
__device__ float g_ctxS[HEADS_TOTAL * 272];

// ---------------------------------------------------------------------------
// Pass 1: unnormalized context ctxU[k][v] = sum_n exp(k[k][n]) * v[v][n]
//         and S[k] = sum_n exp(k[k][n]).  One streaming pass over x1 + x2.
// Block: 256 threads = 4 k-groups (kg) x 64 n-lanes (tn). Each thread owns a
// 4k x 16v accumulator tile; float4 along n.
// ---------------------------------------------------------------------------
__global__ __launch_bounds__(256, 2)
void k1_partial(const float* __restrict__ v_in, const float* __restrict__ k_in) {
    const int head  = blockIdx.y;
    const int chunk = blockIdx.x;
    const int t  = threadIdx.x;
    const int kg = t >> 6;   // 0..3 -> k channels kg*4 .. kg*4+3
    const int tn = t & 63;   // 0..63

    const float* kbase = k_in + (size_t)head * CH * NN;
    const float* vbase = v_in + (size_t)head * CH * NN;
    const int n0 = chunk * CN;

    float acc[4][16];
#pragma unroll
    for (int i = 0; i < 4; i++)
#pragma unroll
        for (int vv = 0; vv < 16; vv++) acc[i][vv] = 0.0f;

    float4 sS4[4];
#pragma unroll
    for (int i = 0; i < 4; i++) sS4[i] = make_float4(0.f, 0.f, 0.f, 0.f);

#pragma unroll 2
    for (int j = 0; j < CN / 256; j++) {          // 8 iterations
        const int n = n0 + j * 256 + tn * 4;
        float4 e4[4];
#pragma unroll
        for (int i = 0; i < 4; i++) {
            float4 kv = *(const float4*)(kbase + (size_t)(kg * 4 + i) * NN + n);
            e4[i].x = __expf(kv.x);
            e4[i].y = __expf(kv.y);
            e4[i].z = __expf(kv.z);
            e4[i].w = __expf(kv.w);
            sS4[i].x += e4[i].x; sS4[i].y += e4[i].y;
            sS4[i].z += e4[i].z; sS4[i].w += e4[i].w;
        }
#pragma unroll
        for (int vv = 0; vv < 16; vv++) {
            float4 v4 = *(const float4*)(vbase + (size_t)vv * NN + n);
#pragma unroll
            for (int i = 0; i < 4; i++) {
                acc[i][vv] += e4[i].x * v4.x;
                acc[i][vv] += e4[i].y * v4.y;
                acc[i][vv] += e4[i].z * v4.z;
                acc[i][vv] += e4[i].w * v4.w;
            }
        }
    }

    // ---- warp reduction (tn spans lanes within each warp) ----
    float sval[4];
#pragma unroll
    for (int i = 0; i < 4; i++) {
#pragma unroll
        for (int vv = 0; vv < 16; vv++) {
            float x = acc[i][vv];
            x += __shfl_down_sync(0xffffffffu, x, 16);
            x += __shfl_down_sync(0xffffffffu, x, 8);
            x += __shfl_down_sync(0xffffffffu, x, 4);
            x += __shfl_down_sync(0xffffffffu, x, 2);
            x += __shfl_down_sync(0xffffffffu, x, 1);
            acc[i][vv] = x;
        }
        float s = sS4[i].x + sS4[i].y + sS4[i].z + sS4[i].w;
        s += __shfl_down_sync(0xffffffffu, s, 16);
        s += __shfl_down_sync(0xffffffffu, s, 8);
        s += __shfl_down_sync(0xffffffffu, s, 4);
        s += __shfl_down_sync(0xffffffffu, s, 2);
        s += __shfl_down_sync(0xffffffffu, s, 1);
        sval[i] = s;
    }

    __shared__ float red[8][68];
    const int warp = t >> 5;
    const int lane = t & 31;
    if (lane == 0) {
#pragma unroll
        for (int i = 0; i < 4; i++) {
#pragma unroll
            for (int vv = 0; vv < 16; vv++) red[warp][i * 16 + vv] = acc[i][vv];
            red[warp][64 + i] = sval[i];
        }
    }
    __syncthreads();

    // Combine the two warps of each kg group and emit in final layout.
    // 272 work items over 256 threads -> strided loop (BUGFIX: t<272 with 256
    // threads previously left the 16 S slots unwritten -> S=0 -> inf/NaN).
    for (int idx = t; idx < 272; idx += 256) {
        int kg2, j;
        if (idx < 256) {
            const int kk = idx >> 4, vv = idx & 15;
            kg2 = kk >> 2;
            j = (kk & 3) * 16 + vv;
        } else {
            const int kk = idx - 256;
            kg2 = kk >> 2;
            j = 64 + (kk & 3);
        }
        const float sum = red[2 * kg2][j] + red[2 * kg2 + 1][j];
        g_part[((size_t)head * CHUNKS + chunk) * 272 + idx] = sum;
    }
}

// ---------------------------------------------------------------------------
// Pass 1b: deterministic reduction over the 8 chunks.
// ---------------------------------------------------------------------------
__global__ void k1_reduce() {
    const int g = blockIdx.x * 256 + threadIdx.x;
    if (g >= HEADS_TOTAL * 272) return;
    const int head = g / 272;
    const int o    = g % 272;
    float s = 0.0f;
#pragma unroll
    for (int c = 0; c < CHUNKS; c++)
        s += g_part[((size_t)head * CHUNKS + c) * 272 + o];
    g_ctxS[g] = s;
}

// ---------------------------------------------------------------------------
// Pass 2: out[v][n] = (1/sum_k e_k) * sum_k (ctxU[k][v]/S[k]) * e_k,
//         e_k = exp(k[k][n]).  One streaming pass over x2, writes output.
// Block: 256 threads, each handles 4 consecutive n (float4). Normalized ctx
// lives in smem, loaded as float4 broadcasts.
// ---------------------------------------------------------------------------
__global__ __launch_bounds__(256, 2)
void k2_out(const float* __restrict__ k_in, float* __restrict__ out) {
    const int head = blockIdx.y;
    const int t = threadIdx.x;

    __shared__ float cn[256];      // cn[k*16+v] = ctxU[k][v] / S[k]
    {
        const int kk = t >> 4;
        const float S = g_ctxS[(size_t)head * 272 + 256 + kk];
        cn[t] = g_ctxS[(size_t)head * 272 + t] / S;
    }
    __syncthreads();

    const float* kbase = k_in + (size_t)head * CH * NN;
    float* obase = out + (size_t)head * CH * NN;
    const int n = blockIdx.x * 1024 + t * 4;

    float4 acc[16];
#pragma unroll
    for (int v = 0; v < 16; v++) acc[v] = make_float4(0.f, 0.f, 0.f, 0.f);
    float4 esum = make_float4(0.f, 0.f, 0.f, 0.f);

#pragma unroll
    for (int c = 0; c < 16; c++) {
        float4 kv = *(const float4*)(kbase + (size_t)c * NN + n);
        float4 e;
        e.x = __expf(kv.x); e.y = __expf(kv.y);
        e.z = __expf(kv.z); e.w = __expf(kv.w);
        esum.x += e.x; esum.y += e.y; esum.z += e.z; esum.w += e.w;

        const float4* c4p = (const float4*)&cn[c * 16];
#pragma unroll
        for (int vg = 0; vg < 4; vg++) {
            const float4 c4 = c4p[vg];
            float4* a0 = &acc[vg * 4 + 0];
            float4* a1 = &acc[vg * 4 + 1];
            float4* a2 = &acc[vg * 4 + 2];
            float4* a3 = &acc[vg * 4 + 3];
            a0->x += c4.x * e.x; a0->y += c4.x * e.y; a0->z += c4.x * e.z; a0->w += c4.x * e.w;
            a1->x += c4.y * e.x; a1->y += c4.y * e.y; a1->z += c4.y * e.z; a1->w += c4.y * e.w;
            a2->x += c4.z * e.x; a2->y += c4.z * e.y; a2->z += c4.z * e.z; a2->w += c4.z * e.w;
            a3->x += c4.w * e.x; a3->y += c4.w * e.y; a3->z += c4.w * e.z; a3->w += c4.w * e.w;
        }
    }

    float4 inv;
    inv.x = 1.0f / esum.x; inv.y = 1.0f / esum.y;
    inv.z = 1.0f / esum.z; inv.w = 1.0f / esum.w;

#pragma unroll
    for (int v = 0; v < 16; v++) {
        float4 o4;
        o4.x = acc[v].x * inv.x;
        o4.y = acc[v].y * inv.y;
        o4.z = acc[v].z * inv.z;
        o4.w = acc[v].w * inv.w;
        *(float4*)(obase + (size_t)v * NN + n) = o4;
    }
}

// ---------------------------------------------------------------------------
extern "C" void kernel_launch(void* const* d_in, const int* in_sizes, int n_in,
                              void* d_out, int out_size) {
    const float* x1 = (const float*)d_in[0];   // values (v)
    const float* x2 = (const float*)d_in[1];   // keys/queries (k)
    float* out = (float*)d_out;

    k1_partial<<<dim3(CHUNKS, HEADS_TOTAL), 256>>>(x1, x2);
    k1_reduce<<<(HEADS_TOTAL * 272 + 255) / 256, 256>>>();
    k2_out<<<dim3(NN / 1024, HEADS_TOTAL), 256>>>(x2, out);
}

// round 4
// speedup vs baseline: 1.1203x; 1.1203x over previous
#include <cuda_runtime.h>
#include <cstdint>

// Problem constants: B=8, C=128, H=W=128, HEADS=8
#define HEADS_TOTAL 64     // B * HEADS
#define CH 16              // channels per head (hk = hv = 16)
#define NN 16384           // H * W
#define CHUNKS 16          // n-chunks per head in pass 1
#define CN (NN / CHUNKS)   // 1024 n per chunk
#define REC 272            // per-(head,chunk) record: 256 ctxU + 16 S

// Scratch: per-(head,chunk) partials. k2 reduces chunks itself.
__device__ float g_part[HEADS_TOTAL * CHUNKS * REC];

// ---------------------------------------------------------------------------
// Pass 1: ctxU[k][v] = sum_n exp(k[k][n]) * v[v][n];  S[k] = sum_n exp(k[k][n])
// Block: 256 threads = 8 warps, warp w -> (kg = w>>1 in 0..3, vg = w&1 in 0..1)
// Thread tile: 4 k-channels x 8 v-channels (32 scalar accumulators), float4
// along n. k lines shared by 2 warps, v lines by 4 warps (L1 dedup).
// ---------------------------------------------------------------------------
__global__ __launch_bounds__(256, 3)
void k1_partial(const float* __restrict__ v_in, const float* __restrict__ k_in) {
    const int head  = blockIdx.y;
    const int chunk = blockIdx.x;
    const int t = threadIdx.x;
    const int w = t >> 5, lane = t & 31;
    const int kg = w >> 1;   // k channels kg*4 .. kg*4+3
    const int vg = w & 1;    // v channels vg*8 .. vg*8+7

    const float* kb = k_in + (size_t)head * CH * NN + (size_t)(kg * 4) * NN;
    const float* vb = v_in + (size_t)head * CH * NN + (size_t)(vg * 8) * NN;
    const int n0 = chunk * CN + lane * 4;

    float acc[4][8];
    float s[4];
#pragma unroll
    for (int i = 0; i < 4; i++) {
        s[i] = 0.0f;
#pragma unroll
        for (int u = 0; u < 8; u++) acc[i][u] = 0.0f;
    }

#pragma unroll 2
    for (int j = 0; j < CN / 128; j++) {     // 8 iterations, 128 n per pass
        const int n = n0 + j * 128;
        float4 e[4];
#pragma unroll
        for (int i = 0; i < 4; i++) {
            float4 kv = *(const float4*)(kb + (size_t)i * NN + n);
            e[i].x = __expf(kv.x);
            e[i].y = __expf(kv.y);
            e[i].z = __expf(kv.z);
            e[i].w = __expf(kv.w);
            s[i] += (e[i].x + e[i].y) + (e[i].z + e[i].w);
        }
#pragma unroll
        for (int u = 0; u < 8; u++) {
            float4 v4 = *(const float4*)(vb + (size_t)u * NN + n);
#pragma unroll
            for (int i = 0; i < 4; i++) {
                acc[i][u] += e[i].x * v4.x;
                acc[i][u] += e[i].y * v4.y;
                acc[i][u] += e[i].z * v4.z;
                acc[i][u] += e[i].w * v4.w;
            }
        }
    }

    // Warp-level reduction across the 32 n-lanes.
#pragma unroll
    for (int i = 0; i < 4; i++) {
#pragma unroll
        for (int u = 0; u < 8; u++) {
            float x = acc[i][u];
            x += __shfl_down_sync(0xffffffffu, x, 16);
            x += __shfl_down_sync(0xffffffffu, x, 8);
            x += __shfl_down_sync(0xffffffffu, x, 4);
            x += __shfl_down_sync(0xffffffffu, x, 2);
            x += __shfl_down_sync(0xffffffffu, x, 1);
            acc[i][u] = x;
        }
        float x = s[i];
        x += __shfl_down_sync(0xffffffffu, x, 16);
        x += __shfl_down_sync(0xffffffffu, x, 8);
        x += __shfl_down_sync(0xffffffffu, x, 4);
        x += __shfl_down_sync(0xffffffffu, x, 2);
        x += __shfl_down_sync(0xffffffffu, x, 1);
        s[i] = x;
    }

    __shared__ float red[REC];
    if (lane == 0) {
#pragma unroll
        for (int i = 0; i < 4; i++) {
#pragma unroll
            for (int u = 0; u < 8; u++)
                red[(kg * 4 + i) * 16 + vg * 8 + u] = acc[i][u];
            if (vg == 0) red[256 + kg * 4 + i] = s[i];
        }
    }
    __syncthreads();

    float* dst = g_part + ((size_t)head * CHUNKS + chunk) * REC;
    for (int idx = t; idx < REC; idx += 256) dst[idx] = red[idx];
}

// ---------------------------------------------------------------------------
// Pass 2 (fused chunk-reduce + output):
//   out[v][n] = (1/sum_k e_k) * sum_k (ctxU[k][v]/S[k]) * e_k
// Block: 256 threads = 2 v-groups x 128 n-lanes; thread tile 8v x 4n.
// Prologue: deterministically reduce the 16 chunk partials into smem and
// normalize by S[k].
// ---------------------------------------------------------------------------
__global__ __launch_bounds__(256, 3)
void k2_out(const float* __restrict__ k_in, float* __restrict__ out) {
    const int head = blockIdx.y;
    const int t = threadIdx.x;

    __shared__ float raw[REC];
    __shared__ float cn[256];    // cn[k*16+v] = ctxU[k][v] / S[k]

    {
        const float* src = g_part + (size_t)head * CHUNKS * REC;
        for (int idx = t; idx < REC; idx += 256) {
            float ssum = 0.0f;
#pragma unroll
            for (int c = 0; c < CHUNKS; c++) ssum += src[c * REC + idx];
            raw[idx] = ssum;
        }
    }
    __syncthreads();
    cn[t] = raw[t] / raw[256 + (t >> 4)];
    __syncthreads();

    const int vg = t >> 7;       // 0..1 -> v channels vg*8 .. vg*8+7
    const int tn = t & 127;
    const int n = blockIdx.x * 512 + tn * 4;

    const float* kb = k_in + (size_t)head * CH * NN;
    float* ob = out + (size_t)head * CH * NN + (size_t)(vg * 8) * NN;

    float4 acc[8];
#pragma unroll
    for (int u = 0; u < 8; u++) acc[u] = make_float4(0.f, 0.f, 0.f, 0.f);
    float4 esum = make_float4(0.f, 0.f, 0.f, 0.f);

#pragma unroll
    for (int c = 0; c < 16; c++) {
        float4 kv = *(const float4*)(kb + (size_t)c * NN + n);
        float4 e;
        e.x = __expf(kv.x); e.y = __expf(kv.y);
        e.z = __expf(kv.z); e.w = __expf(kv.w);
        esum.x += e.x; esum.y += e.y; esum.z += e.z; esum.w += e.w;

        const float4* cp = (const float4*)&cn[c * 16 + vg * 8];
        const float4 c0 = cp[0];
        const float4 c1 = cp[1];
        acc[0].x += c0.x * e.x; acc[0].y += c0.x * e.y; acc[0].z += c0.x * e.z; acc[0].w += c0.x * e.w;
        acc[1].x += c0.y * e.x; acc[1].y += c0.y * e.y; acc[1].z += c0.y * e.z; acc[1].w += c0.y * e.w;
        acc[2].x += c0.z * e.x; acc[2].y += c0.z * e.y; acc[2].z += c0.z * e.z; acc[2].w += c0.z * e.w;
        acc[3].x += c0.w * e.x; acc[3].y += c0.w * e.y; acc[3].z += c0.w * e.z; acc[3].w += c0.w * e.w;
        acc[4].x += c1.x * e.x; acc[4].y += c1.x * e.y; acc[4].z += c1.x * e.z; acc[4].w += c1.x * e.w;
        acc[5].x += c1.y * e.x; acc[5].y += c1.y * e.y; acc[5].z += c1.y * e.z; acc[5].w += c1.y * e.w;
        acc[6].x += c1.z * e.x; acc[6].y += c1.z * e.y; acc[6].z += c1.z * e.z; acc[6].w += c1.z * e.w;
        acc[7].x += c1.w * e.x; acc[7].y += c1.w * e.y; acc[7].z += c1.w * e.z; acc[7].w += c1.w * e.w;
    }

    float4 inv;
    inv.x = 1.0f / esum.x; inv.y = 1.0f / esum.y;
    inv.z = 1.0f / esum.z; inv.w = 1.0f / esum.w;

#pragma unroll
    for (int u = 0; u < 8; u++) {
        float4 o4;
        o4.x = acc[u].x * inv.x;
        o4.y = acc[u].y * inv.y;
        o4.z = acc[u].z * inv.z;
        o4.w = acc[u].w * inv.w;
        *(float4*)(ob + (size_t)u * NN + n) = o4;
    }
}

// ---------------------------------------------------------------------------
extern "C" void kernel_launch(void* const* d_in, const int* in_sizes, int n_in,
                              void* d_out, int out_size) {
    const float* x1 = (const float*)d_in[0];   // values (v)
    const float* x2 = (const float*)d_in[1];   // keys/queries (k)
    float* out = (float*)d_out;

    k1_partial<<<dim3(CHUNKS, HEADS_TOTAL), 256>>>(x1, x2);
    k2_out<<<dim3(NN / 512, HEADS_TOTAL), 256>>>(x2, out);
}

// round 5
// speedup vs baseline: 1.1265x; 1.0056x over previous
#include <cuda_runtime.h>
#include <cstdint>

// Problem constants: B=8, C=128, H=W=128, HEADS=8
#define HEADS_TOTAL 64     // B * HEADS
#define CH 16              // channels per head (hk = hv = 16)
#define NN 16384           // H * W
#define CHUNKS 16          // n-chunks per head in pass 1
#define CN (NN / CHUNKS)   // 1024 n per chunk
#define REC 272            // per-(head,chunk) record: 256 ctxU + 16 S

// Scratch: per-(head,chunk) partials. k2 reduces chunks itself.
__device__ float g_part[HEADS_TOTAL * CHUNKS * REC];

// ---------------------------------------------------------------------------
// Pass 1: ctxU[k][v] = sum_n exp(k[k][n]) * v[v][n];  S[k] = sum_n exp(k[k][n])
// Block: 256 threads = 8 warps, warp w -> (kg = w>>1 in 0..3, vg = w&1 in 0..1)
// Thread tile: 4 k-channels x 8 v-channels (32 scalar accumulators), float4
// along n. k lines shared by 2 warps, v lines by 4 warps (L1 dedup).
// ---------------------------------------------------------------------------
__global__ __launch_bounds__(256, 3)
void k1_partial(const float* __restrict__ v_in, const float* __restrict__ k_in) {
    const int head  = blockIdx.y;
    const int chunk = blockIdx.x;
    const int t = threadIdx.x;
    const int w = t >> 5, lane = t & 31;
    const int kg = w >> 1;   // k channels kg*4 .. kg*4+3
    const int vg = w & 1;    // v channels vg*8 .. vg*8+7

    const float* kb = k_in + (size_t)head * CH * NN + (size_t)(kg * 4) * NN;
    const float* vb = v_in + (size_t)head * CH * NN + (size_t)(vg * 8) * NN;
    const int n0 = chunk * CN + lane * 4;

    float acc[4][8];
    float s[4];
#pragma unroll
    for (int i = 0; i < 4; i++) {
        s[i] = 0.0f;
#pragma unroll
        for (int u = 0; u < 8; u++) acc[i][u] = 0.0f;
    }

#pragma unroll 2
    for (int j = 0; j < CN / 128; j++) {     // 8 iterations, 128 n per pass
        const int n = n0 + j * 128;
        float4 e[4];
#pragma unroll
        for (int i = 0; i < 4; i++) {
            float4 kv = *(const float4*)(kb + (size_t)i * NN + n);
            e[i].x = __expf(kv.x);
            e[i].y = __expf(kv.y);
            e[i].z = __expf(kv.z);
            e[i].w = __expf(kv.w);
            s[i] += (e[i].x + e[i].y) + (e[i].z + e[i].w);
        }
#pragma unroll
        for (int u = 0; u < 8; u++) {
            float4 v4 = *(const float4*)(vb + (size_t)u * NN + n);
#pragma unroll
            for (int i = 0; i < 4; i++) {
                acc[i][u] += e[i].x * v4.x;
                acc[i][u] += e[i].y * v4.y;
                acc[i][u] += e[i].z * v4.z;
                acc[i][u] += e[i].w * v4.w;
            }
        }
    }

    // Warp-level reduction across the 32 n-lanes.
#pragma unroll
    for (int i = 0; i < 4; i++) {
#pragma unroll
        for (int u = 0; u < 8; u++) {
            float x = acc[i][u];
            x += __shfl_down_sync(0xffffffffu, x, 16);
            x += __shfl_down_sync(0xffffffffu, x, 8);
            x += __shfl_down_sync(0xffffffffu, x, 4);
            x += __shfl_down_sync(0xffffffffu, x, 2);
            x += __shfl_down_sync(0xffffffffu, x, 1);
            acc[i][u] = x;
        }
        float x = s[i];
        x += __shfl_down_sync(0xffffffffu, x, 16);
        x += __shfl_down_sync(0xffffffffu, x, 8);
        x += __shfl_down_sync(0xffffffffu, x, 4);
        x += __shfl_down_sync(0xffffffffu, x, 2);
        x += __shfl_down_sync(0xffffffffu, x, 1);
        s[i] = x;
    }

    __shared__ float red[REC];
    if (lane == 0) {
#pragma unroll
        for (int i = 0; i < 4; i++) {
#pragma unroll
            for (int u = 0; u < 8; u++)
                red[(kg * 4 + i) * 16 + vg * 8 + u] = acc[i][u];
            if (vg == 0) red[256 + kg * 4 + i] = s[i];
        }
    }
    __syncthreads();

    float* dst = g_part + ((size_t)head * CHUNKS + chunk) * REC;
    for (int idx = t; idx < REC; idx += 256) dst[idx] = red[idx];
}

// ---------------------------------------------------------------------------
// Pass 2 (fused chunk-reduce + output):
//   out[v][n] = (1/sum_k e_k) * sum_k (ctxU[k][v]/S[k]) * e_k
// Block: 256 threads = 2 v-groups x 128 n-lanes; thread tile 8v x 4n.
// Prologue: deterministically reduce the 16 chunk partials into smem and
// normalize by S[k].
// ---------------------------------------------------------------------------
__global__ __launch_bounds__(256, 3)
void k2_out(const float* __restrict__ k_in, float* __restrict__ out) {
    const int head = blockIdx.y;
    const int t = threadIdx.x;

    __shared__ float raw[REC];
    __shared__ float cn[256];    // cn[k*16+v] = ctxU[k][v] / S[k]

    {
        const float* src = g_part + (size_t)head * CHUNKS * REC;
        for (int idx = t; idx < REC; idx += 256) {
            float ssum = 0.0f;
#pragma unroll
            for (int c = 0; c < CHUNKS; c++) ssum += src[c * REC + idx];
            raw[idx] = ssum;
        }
    }
    __syncthreads();
    cn[t] = raw[t] / raw[256 + (t >> 4)];
    __syncthreads();

    const int vg = t >> 7;       // 0..1 -> v channels vg*8 .. vg*8+7
    const int tn = t & 127;
    const int n = blockIdx.x * 512 + tn * 4;

    const float* kb = k_in + (size_t)head * CH * NN;
    float* ob = out + (size_t)head * CH * NN + (size_t)(vg * 8) * NN;

    float4 acc[8];
#pragma unroll
    for (int u = 0; u < 8; u++) acc[u] = make_float4(0.f, 0.f, 0.f, 0.f);
    float4 esum = make_float4(0.f, 0.f, 0.f, 0.f);

#pragma unroll
    for (int c = 0; c < 16; c++) {
        float4 kv = *(const float4*)(kb + (size_t)c * NN + n);
        float4 e;
        e.x = __expf(kv.x); e.y = __expf(kv.y);
        e.z = __expf(kv.z); e.w = __expf(kv.w);
        esum.x += e.x; esum.y += e.y; esum.z += e.z; esum.w += e.w;

        const float4* cp = (const float4*)&cn[c * 16 + vg * 8];
        const float4 c0 = cp[0];
        const float4 c1 = cp[1];
        acc[0].x += c0.x * e.x; acc[0].y += c0.x * e.y; acc[0].z += c0.x * e.z; acc[0].w += c0.x * e.w;
        acc[1].x += c0.y * e.x; acc[1].y += c0.y * e.y; acc[1].z += c0.y * e.z; acc[1].w += c0.y * e.w;
        acc[2].x += c0.z * e.x; acc[2].y += c0.z * e.y; acc[2].z += c0.z * e.z; acc[2].w += c0.z * e.w;
        acc[3].x += c0.w * e.x; acc[3].y += c0.w * e.y; acc[3].z += c0.w * e.z; acc[3].w += c0.w * e.w;
        acc[4].x += c1.x * e.x; acc[4].y += c1.x * e.y; acc[4].z += c1.x * e.z; acc[4].w += c1.x * e.w;
        acc[5].x += c1.y * e.x; acc[5].y += c1.y * e.y; acc[5].z += c1.y * e.z; acc[5].w += c1.y * e.w;
        acc[6].x += c1.z * e.x; acc[6].y += c1.z * e.y; acc[6].z += c1.z * e.z; acc[6].w += c1.z * e.w;
        acc[7].x += c1.w * e.x; acc[7].y += c1.w * e.y; acc[7].z += c1.w * e.z; acc[7].w += c1.w * e.w;
    }

    float4 inv;
    inv.x = 1.0f / esum.x; inv.y = 1.0f / esum.y;
    inv.z = 1.0f / esum.z; inv.w = 1.0f / esum.w;

#pragma unroll
    for (int u = 0; u < 8; u++) {
        float4 o4;
        o4.x = acc[u].x * inv.x;
        o4.y = acc[u].y * inv.y;
        o4.z = acc[u].z * inv.z;
        o4.w = acc[u].w * inv.w;
        *(float4*)(ob + (size_t)u * NN + n) = o4;
    }
}

// ---------------------------------------------------------------------------
extern "C" void kernel_launch(void* const* d_in, const int* in_sizes, int n_in,
                              void* d_out, int out_size) {
    const float* x1 = (const float*)d_in[0];   // values (v)
    const float* x2 = (const float*)d_in[1];   // keys/queries (k)
    float* out = (float*)d_out;

    k1_partial<<<dim3(CHUNKS, HEADS_TOTAL), 256>>>(x1, x2);
    k2_out<<<dim3(NN / 512, HEADS_TOTAL), 256>>>(x2, out);
}